// round 3
// baseline (speedup 1.0000x reference)
#include <cuda_runtime.h>
#include <cuda_bf16.h>

// DistortionLoss (eff_distloss) — single fused kernel for GB300.
//
// R2 -> R3: keep the single-kernel last-block-done fusion (saved ~7us of aux
// launches), REVERT the R2 loop-body changes that cost ~10us:
//  - no manual double-buffering (regs 43 -> ~32, occupancy back up; ptxas
//    already front-batches the 3x float4 loads per iteration)
//  - plain cached loads instead of __ldcs
//  - grid back to 4096 blocks (8 rows per warp)

#define LOSS_WEIGHT 0.01f
#define N_SAMPLES 128
#define GRID_MAX 4096
#define BLOCK_THREADS 256

__device__ double   g_partials[GRID_MAX];
__device__ unsigned g_ticket = 0;   // self-resetting via atomicInc wrap

__global__ __launch_bounds__(BLOCK_THREADS) void dl_fused_kernel(
    const float* __restrict__ w,
    const float* __restrict__ m,
    const float* __restrict__ s,
    float* __restrict__ out,
    int B, float scale)
{
    const int lane   = threadIdx.x & 31;
    const int warpIn = threadIdx.x >> 5;
    const int gwarp  = (blockIdx.x * BLOCK_THREADS + threadIdx.x) >> 5;
    const int nwarps = (gridDim.x * BLOCK_THREADS) >> 5;

    float acc = 0.0f;

    for (int row = gwarp; row < B; row += nwarps) {
        const size_t base = (size_t)row * N_SAMPLES;
        const float4 wv = reinterpret_cast<const float4*>(w + base)[lane];
        const float4 mv = reinterpret_cast<const float4*>(m + base)[lane];
        const float4 sv = reinterpret_cast<const float4*>(s + base)[lane];

        // uni term partial: sum s*w^2 over this lane's 4 elements
        float uni = sv.x * wv.x * wv.x;
        uni = fmaf(sv.y * wv.y, wv.y, uni);
        uni = fmaf(sv.z * wv.z, wv.z, uni);
        uni = fmaf(sv.w * wv.w, wv.w, uni);

        // wm = w * m
        const float wm0 = wv.x * mv.x;
        const float wm1 = wv.y * mv.y;
        const float wm2 = wv.z * mv.z;
        const float wm3 = wv.w * mv.w;

        // local exclusive prefixes within the 4-element chunk
        const float eW1 = wv.x;
        const float eW2 = eW1 + wv.y;
        const float eW3 = eW2 + wv.z;
        const float tW  = eW3 + wv.w;     // lane total of w

        const float eM1 = wm0;
        const float eM2 = eM1 + wm1;
        const float eM3 = eM2 + wm2;
        const float tM  = eM3 + wm3;      // lane total of wm

        // warp inclusive scan of lane totals (w and wm together)
        float iW = tW, iM = tM;
        #pragma unroll
        for (int off = 1; off < 32; off <<= 1) {
            const float aW = __shfl_up_sync(0xffffffffu, iW, off);
            const float aM = __shfl_up_sync(0xffffffffu, iM, off);
            if (lane >= off) { iW += aW; iM += aM; }
        }
        const float EW = iW - tW;   // exclusive warp prefix of w
        const float EM = iM - tM;   // exclusive warp prefix of wm

        // bi term: sum_k wm_k * exW_k - w_k * exWM_k  (exclusive prefixes)
        float bi;
        bi  = wm0 * EW          - wv.x * EM;
        bi += wm1 * (EW + eW1)  - wv.y * (EM + eM1);
        bi += wm2 * (EW + eW2)  - wv.z * (EM + eM2);
        bi += wm3 * (EW + eW3)  - wv.w * (EM + eM3);

        acc += (1.0f / 3.0f) * uni + 2.0f * bi;
    }

    // warp reduce
    #pragma unroll
    for (int off = 16; off > 0; off >>= 1)
        acc += __shfl_down_sync(0xffffffffu, acc, off);

    __shared__ float warp_sums[BLOCK_THREADS / 32];
    if (lane == 0) warp_sums[warpIn] = acc;
    __syncthreads();

    __shared__ bool is_last;
    if (threadIdx.x == 0) {
        float blockAcc = 0.0f;
        #pragma unroll
        for (int i = 0; i < BLOCK_THREADS / 32; i++) blockAcc += warp_sums[i];
        g_partials[blockIdx.x] = (double)blockAcc;
        __threadfence();
        // atomicInc wraps to 0 after gridDim.x increments -> counter is 0
        // again at the end of every launch (no init kernel needed).
        const unsigned ticket = atomicInc(&g_ticket, gridDim.x - 1);
        is_last = (ticket == gridDim.x - 1);
    }
    __syncthreads();

    if (is_last) {
        __threadfence();
        double t = 0.0;
        for (int i = threadIdx.x; i < (int)gridDim.x; i += BLOCK_THREADS)
            t += g_partials[i];
        // warp reduce (double)
        #pragma unroll
        for (int off = 16; off > 0; off >>= 1)
            t += __shfl_down_sync(0xffffffffu, t, off);
        __shared__ double dsums[BLOCK_THREADS / 32];
        if (lane == 0) dsums[warpIn] = t;
        __syncthreads();
        if (threadIdx.x == 0) {
            double total = 0.0;
            #pragma unroll
            for (int i = 0; i < BLOCK_THREADS / 32; i++) total += dsums[i];
            out[0] = (float)(total * (double)scale);
        }
    }
}

extern "C" void kernel_launch(void* const* d_in, const int* in_sizes, int n_in,
                              void* d_out, int out_size) {
    const float* w = (const float*)d_in[0];
    const float* m = (const float*)d_in[1];
    const float* s = (const float*)d_in[2];
    float* out = (float*)d_out;

    const int B = in_sizes[0] / N_SAMPLES;

    const int warpsPerBlock = BLOCK_THREADS / 32;
    int blocks = (B + 8 * warpsPerBlock - 1) / (8 * warpsPerBlock);  // 8 rows/warp
    if (blocks > GRID_MAX) blocks = GRID_MAX;
    if (blocks < 1) blocks = 1;

    dl_fused_kernel<<<blocks, BLOCK_THREADS>>>(w, m, s, out, B,
                                               LOSS_WEIGHT / (float)B);
}

// round 5
// speedup vs baseline: 1.0312x; 1.0312x over previous
#include <cuda_runtime.h>
#include <cuda_bf16.h>

// DistortionLoss (eff_distloss) — single fused kernel, row-pair unrolled.
//
// R3 -> R4: all rounds plateau at ~6TB/s (75% HBM) with only 3 independent
// LDG.128 per warp-iteration. Unroll the grid-stride row loop by 2: each warp
// loads SIX independent float4s (two consecutive rows x three arrays) before
// computing either row's contribution -> 2x bytes in flight per warp and
// better DRAM page locality (rows 2k,2k+1 are contiguous 1KB per array).
// Keep single-kernel last-block-done reduction (ticket wraps to 0 each call).

#define LOSS_WEIGHT 0.01f
#define N_SAMPLES 128
#define GRID_MAX 4096
#define BLOCK_THREADS 256

__device__ double   g_partials[GRID_MAX];
__device__ unsigned g_ticket = 0;   // self-resetting via atomicInc wrap

__device__ __forceinline__ float row_contrib(
    const float4 wv, const float4 mv, const float4 sv, const int lane)
{
    // uni term partial: sum s*w^2 over this lane's 4 elements
    float uni = sv.x * wv.x * wv.x;
    uni = fmaf(sv.y * wv.y, wv.y, uni);
    uni = fmaf(sv.z * wv.z, wv.z, uni);
    uni = fmaf(sv.w * wv.w, wv.w, uni);

    // wm = w * m
    const float wm0 = wv.x * mv.x;
    const float wm1 = wv.y * mv.y;
    const float wm2 = wv.z * mv.z;
    const float wm3 = wv.w * mv.w;

    // local exclusive prefixes within the 4-element chunk
    const float eW1 = wv.x;
    const float eW2 = eW1 + wv.y;
    const float eW3 = eW2 + wv.z;
    const float tW  = eW3 + wv.w;     // lane total of w

    const float eM1 = wm0;
    const float eM2 = eM1 + wm1;
    const float eM3 = eM2 + wm2;
    const float tM  = eM3 + wm3;      // lane total of wm

    // warp inclusive scan of lane totals (w and wm scanned together)
    float iW = tW, iM = tM;
    #pragma unroll
    for (int off = 1; off < 32; off <<= 1) {
        const float aW = __shfl_up_sync(0xffffffffu, iW, off);
        const float aM = __shfl_up_sync(0xffffffffu, iM, off);
        if (lane >= off) { iW += aW; iM += aM; }
    }
    const float EW = iW - tW;   // exclusive warp prefix of w
    const float EM = iM - tM;   // exclusive warp prefix of wm

    // bi term: sum_k wm_k * exW_k - w_k * exWM_k  (exclusive prefixes)
    float bi;
    bi  = wm0 * EW          - wv.x * EM;
    bi += wm1 * (EW + eW1)  - wv.y * (EM + eM1);
    bi += wm2 * (EW + eW2)  - wv.z * (EM + eM2);
    bi += wm3 * (EW + eW3)  - wv.w * (EM + eM3);

    return (1.0f / 3.0f) * uni + 2.0f * bi;
}

__global__ __launch_bounds__(BLOCK_THREADS) void dl_fused_kernel(
    const float* __restrict__ w,
    const float* __restrict__ m,
    const float* __restrict__ s,
    float* __restrict__ out,
    int B, float scale)
{
    const int lane   = threadIdx.x & 31;
    const int warpIn = threadIdx.x >> 5;
    const int gwarp  = (blockIdx.x * BLOCK_THREADS + threadIdx.x) >> 5;
    const int nwarps = (gridDim.x * BLOCK_THREADS) >> 5;

    float acc = 0.0f;

    // Row-pair loop: warp handles rows (2g, 2g+1), stride 2*nwarps.
    int row = 2 * gwarp;
    for (; row + 1 < B; row += 2 * nwarps) {
        const size_t b0 = (size_t)row * N_SAMPLES;
        const size_t b1 = b0 + N_SAMPLES;
        // 6 independent 16B loads issued before any compute
        const float4 wv0 = reinterpret_cast<const float4*>(w + b0)[lane];
        const float4 wv1 = reinterpret_cast<const float4*>(w + b1)[lane];
        const float4 mv0 = reinterpret_cast<const float4*>(m + b0)[lane];
        const float4 mv1 = reinterpret_cast<const float4*>(m + b1)[lane];
        const float4 sv0 = reinterpret_cast<const float4*>(s + b0)[lane];
        const float4 sv1 = reinterpret_cast<const float4*>(s + b1)[lane];

        acc += row_contrib(wv0, mv0, sv0, lane);
        acc += row_contrib(wv1, mv1, sv1, lane);
    }
    if (row < B) {  // odd-B tail
        const size_t b0 = (size_t)row * N_SAMPLES;
        const float4 wv0 = reinterpret_cast<const float4*>(w + b0)[lane];
        const float4 mv0 = reinterpret_cast<const float4*>(m + b0)[lane];
        const float4 sv0 = reinterpret_cast<const float4*>(s + b0)[lane];
        acc += row_contrib(wv0, mv0, sv0, lane);
    }

    // warp reduce
    #pragma unroll
    for (int off = 16; off > 0; off >>= 1)
        acc += __shfl_down_sync(0xffffffffu, acc, off);

    __shared__ float warp_sums[BLOCK_THREADS / 32];
    if (lane == 0) warp_sums[warpIn] = acc;
    __syncthreads();

    __shared__ bool is_last;
    if (threadIdx.x == 0) {
        float blockAcc = 0.0f;
        #pragma unroll
        for (int i = 0; i < BLOCK_THREADS / 32; i++) blockAcc += warp_sums[i];
        g_partials[blockIdx.x] = (double)blockAcc;
        __threadfence();
        const unsigned ticket = atomicInc(&g_ticket, gridDim.x - 1);
        is_last = (ticket == gridDim.x - 1);
    }
    __syncthreads();

    if (is_last) {
        __threadfence();
        double t = 0.0;
        for (int i = threadIdx.x; i < (int)gridDim.x; i += BLOCK_THREADS)
            t += g_partials[i];
        #pragma unroll
        for (int off = 16; off > 0; off >>= 1)
            t += __shfl_down_sync(0xffffffffu, t, off);
        __shared__ double dsums[BLOCK_THREADS / 32];
        if (lane == 0) dsums[warpIn] = t;
        __syncthreads();
        if (threadIdx.x == 0) {
            double total = 0.0;
            #pragma unroll
            for (int i = 0; i < BLOCK_THREADS / 32; i++) total += dsums[i];
            out[0] = (float)(total * (double)scale);
        }
    }
}

extern "C" void kernel_launch(void* const* d_in, const int* in_sizes, int n_in,
                              void* d_out, int out_size) {
    const float* w = (const float*)d_in[0];
    const float* m = (const float*)d_in[1];
    const float* s = (const float*)d_in[2];
    float* out = (float*)d_out;

    const int B = in_sizes[0] / N_SAMPLES;

    const int warpsPerBlock = BLOCK_THREADS / 32;
    // one warp per 2 rows per iteration; target ~8 rows/warp total
    int blocks = (B + 8 * warpsPerBlock - 1) / (8 * warpsPerBlock);
    if (blocks > GRID_MAX) blocks = GRID_MAX;
    if (blocks < 1) blocks = 1;

    dl_fused_kernel<<<blocks, BLOCK_THREADS>>>(w, m, s, out, B,
                                               LOSS_WEIGHT / (float)B);
}